// round 5
// baseline (speedup 1.0000x reference)
#include <cuda_runtime.h>

// Problem-fixed sizes (reference: N=100000, F_IN=512, F_OUT=2).
#define NMAX 100000
#define FOUT 2
#define FIN 512

#define GEMM_BLOCKS 1024
#define DEG_BLOCKS 160   // GEMM_BLOCKS + DEG_BLOCKS = 1184 = 148 SMs * 8 CTAs

__device__ __align__(16) float g_deg[NMAX];
__device__ __align__(16) float g_dis[NMAX];
__device__ __align__(16) float g_h[NMAX * FOUT];    // raw x@W
__device__ __align__(16) float g_hs[NMAX * FOUT];   // h * dis (gather source)
__device__ __align__(16) float g_acc[NMAX * FOUT];  // self-loop + edge sums
__device__ float g_acc_scalar;
__device__ unsigned int g_ticket;

// ---------------------------------------------------------------------------
// K0: zero g_deg (self-loop +1 folded into post), scalar acc, ticket.
__global__ void init_kernel(int n4) {
    int i = blockIdx.x * blockDim.x + threadIdx.x;
    if (i < n4) ((float4*)g_deg)[i] = make_float4(0.f, 0.f, 0.f, 0.f);
    if (i == 0) { g_acc_scalar = 0.0f; g_ticket = 0u; }
}

// ---------------------------------------------------------------------------
// K1 (fused, persistent): blocks [0, GEMM_BLOCKS) grid-stride warp-per-row
// h = x @ W (DRAM-streaming); blocks [GEMM_BLOCKS, +DEG_BLOCKS) grid-stride
// the deg segment-sum atomics (L2 pipe). One wave, no wave transitions.
__global__ __launch_bounds__(256) void fused_gemm_deg(
        const float* __restrict__ x, const float* __restrict__ W, int n,
        const int* __restrict__ col, const float* __restrict__ w, int E) {
    if ((int)blockIdx.x >= GEMM_BLOCKS) {
        // --- deg atomics: grid-stride over quads of edges ---
        int t0 = ((int)blockIdx.x - GEMM_BLOCKS) * 256 + threadIdx.x;
        int nthr = DEG_BLOCKS * 256;
        int nq = E >> 2;
        for (int q = t0; q < nq; q += nthr) {
            int4 c4 = *(const int4*)(col + q * 4);
            float4 w4 = *(const float4*)(w + q * 4);
            atomicAdd(&g_deg[c4.x], w4.x);
            atomicAdd(&g_deg[c4.y], w4.y);
            atomicAdd(&g_deg[c4.z], w4.z);
            atomicAdd(&g_deg[c4.w], w4.w);
        }
        if (t0 == 0) {
            for (int e = nq * 4; e < E; ++e) atomicAdd(&g_deg[col[e]], w[e]);
        }
        return;
    }
    // --- GEMM: persistent warp-per-row; 4 independent LDG.128 per row ---
    __shared__ __align__(16) float sW[FIN * FOUT];
    for (int i = threadIdx.x; i < FIN * FOUT; i += blockDim.x) sW[i] = W[i];
    __syncthreads();

    int warp = threadIdx.x >> 5;
    int lane = threadIdx.x & 31;
    int wid0 = (int)blockIdx.x * 8 + warp;
    const int wstride = GEMM_BLOCKS * 8;
    const float4* sW4 = (const float4*)sW;

    for (int row = wid0; row < n; row += wstride) {
        const float4* xr = (const float4*)(x + (size_t)row * FIN);
        float4 v0 = __ldcs(xr + lane);        // read-once: evict-first
        float4 v1 = __ldcs(xr + lane + 32);
        float4 v2 = __ldcs(xr + lane + 64);
        float4 v3 = __ldcs(xr + lane + 96);

        float a0 = 0.f, a1 = 0.f;
#define ACCUM(v, q)                                                        \
        {                                                                  \
            float4 wa = sW4[2 * (q)];                                      \
            float4 wb = sW4[2 * (q) + 1];                                  \
            a0 += v.x * wa.x + v.y * wa.z + v.z * wb.x + v.w * wb.z;       \
            a1 += v.x * wa.y + v.y * wa.w + v.z * wb.y + v.w * wb.w;       \
        }
        ACCUM(v0, lane)
        ACCUM(v1, lane + 32)
        ACCUM(v2, lane + 64)
        ACCUM(v3, lane + 96)
#undef ACCUM

#pragma unroll
        for (int off = 16; off; off >>= 1) {
            a0 += __shfl_down_sync(0xffffffffu, a0, off);
            a1 += __shfl_down_sync(0xffffffffu, a1, off);
        }
        if (lane == 0) {
            g_h[2 * row + 0] = a0;
            g_h[2 * row + 1] = a1;
        }
    }
}

// ---------------------------------------------------------------------------
// K2: dis = rsqrt(deg + 1); hs = h*dis; acc = hs (self-loop, weight 1).
__global__ void post_kernel(int n) {
    int i = blockIdx.x * blockDim.x + threadIdx.x;
    if (i >= n) return;
    float d = g_deg[i] + 1.0f;  // self-loop weight
    float dis = (d > 0.f) ? rsqrtf(d) : 0.f;
    g_dis[i] = dis;
    float2 h = *(const float2*)(g_h + 2 * i);
    float2 hs = make_float2(h.x * dis, h.y * dis);
    *(float2*)(g_hs + 2 * i) = hs;
    *(float2*)(g_acc + 2 * i) = hs;
}

// ---------------------------------------------------------------------------
// K3: edge scatter: acc[col] += hs[row] * w. One random 8B gather + one v2
// RED per edge; 4 edges/thread for gather ILP.
__global__ __launch_bounds__(256) void edge_kernel(
        const int* __restrict__ row, const int* __restrict__ col,
        const float* __restrict__ w, int E) {
    int t = blockIdx.x * blockDim.x + threadIdx.x;
    int base = t * 4;
    if (base + 3 < E) {
        int4 r4 = *(const int4*)(row + base);
        int4 c4 = *(const int4*)(col + base);
        float4 w4 = *(const float4*)(w + base);
        float2 h0 = __ldg((const float2*)(g_hs + 2 * r4.x));
        float2 h1 = __ldg((const float2*)(g_hs + 2 * r4.y));
        float2 h2 = __ldg((const float2*)(g_hs + 2 * r4.z));
        float2 h3 = __ldg((const float2*)(g_hs + 2 * r4.w));
        asm volatile("red.global.add.v2.f32 [%0], {%1, %2};" ::
                     "l"(g_acc + 2 * c4.x), "f"(h0.x * w4.x), "f"(h0.y * w4.x) : "memory");
        asm volatile("red.global.add.v2.f32 [%0], {%1, %2};" ::
                     "l"(g_acc + 2 * c4.y), "f"(h1.x * w4.y), "f"(h1.y * w4.y) : "memory");
        asm volatile("red.global.add.v2.f32 [%0], {%1, %2};" ::
                     "l"(g_acc + 2 * c4.z), "f"(h2.x * w4.z), "f"(h2.y * w4.z) : "memory");
        asm volatile("red.global.add.v2.f32 [%0], {%1, %2};" ::
                     "l"(g_acc + 2 * c4.w), "f"(h3.x * w4.w), "f"(h3.y * w4.w) : "memory");
    } else {
        for (int e = base; e < E; ++e) {
            int r = row[e], c = col[e];
            float ww = w[e];
            float2 hv = __ldg((const float2*)(g_hs + 2 * r));
            asm volatile("red.global.add.v2.f32 [%0], {%1, %2};" ::
                         "l"(g_acc + 2 * c), "f"(hv.x * ww), "f"(hv.y * ww) : "memory");
        }
    }
}

// ---------------------------------------------------------------------------
// K4: head (+ fused final): relu(dis*acc + b) · fc_w -> g_acc_scalar;
// last block through the ticket applies sigmoid into d_out.
__global__ void head_kernel(const float* __restrict__ bvec,
                            const float* __restrict__ fcw,
                            const float* __restrict__ fcb,
                            float* __restrict__ out, int n, int nblocks) {
    int i = blockIdx.x * blockDim.x + threadIdx.x;
    float p = 0.f;
    if (i < n) {
        float dis = g_dis[i];
        float2 a = *(const float2*)(g_acc + 2 * i);
        float2 fw = *(const float2*)(fcw + 2 * i);
        float v0 = fmaxf(dis * a.x + bvec[0], 0.f);
        float v1 = fmaxf(dis * a.y + bvec[1], 0.f);
        p = v0 * fw.x + v1 * fw.y;
    }
#pragma unroll
    for (int off = 16; off; off >>= 1) p += __shfl_down_sync(0xffffffffu, p, off);
    __shared__ float ws[8];
    __shared__ bool is_last;
    int lane = threadIdx.x & 31, wid = threadIdx.x >> 5;
    if (lane == 0) ws[wid] = p;
    __syncthreads();
    if (wid == 0) {
        p = (lane < (blockDim.x >> 5)) ? ws[lane] : 0.f;
#pragma unroll
        for (int off = 4; off; off >>= 1) p += __shfl_down_sync(0xffffffffu, p, off);
        if (lane == 0) {
            atomicAdd(&g_acc_scalar, p);
            __threadfence();
            unsigned int t = atomicAdd(&g_ticket, 1u);
            is_last = (t == (unsigned int)(nblocks - 1));
        }
    }
    __syncthreads();
    if (is_last && threadIdx.x == 0) {
        float l = g_acc_scalar + fcb[0];
        out[0] = 1.f / (1.f + expf(-l));
    }
}

// ---------------------------------------------------------------------------
extern "C" void kernel_launch(void* const* d_in, const int* in_sizes, int n_in,
                              void* d_out, int out_size) {
    const float* x   = (const float*)d_in[0];      // [N, F_IN]
    const int*   el  = (const int*)d_in[1];        // [2, E] int32 (JAX downcast)
    const float* ea  = (const float*)d_in[2];      // [E]
    const float* W   = (const float*)d_in[3];      // [F_IN, 2]
    const float* b   = (const float*)d_in[4];      // [2]
    const float* fcw = (const float*)d_in[5];      // [2N]
    const float* fcb = (const float*)d_in[6];      // scalar

    int E  = in_sizes[2];
    int n2 = in_sizes[5];
    int n  = n2 / FOUT;

    const int* rowp = el;
    const int* colp = el + E;

    int n4 = (n + 3) / 4;   // float4 count for zeroing g_deg (NMAX%4==0)
    int headB = (n + 255) / 256;

    init_kernel<<<(n4 + 255) / 256, 256>>>(n4);
    fused_gemm_deg<<<GEMM_BLOCKS + DEG_BLOCKS, 256>>>(x, W, n, colp, ea, E);
    post_kernel<<<(n + 255) / 256, 256>>>(n);
    edge_kernel<<<(E / 4 + 255) / 256, 256>>>(rowp, colp, ea, E);
    head_kernel<<<headB, 256>>>(b, fcw, fcb, (float*)d_out, n, headB);
}

// round 6
// speedup vs baseline: 1.6616x; 1.6616x over previous
#include <cuda_runtime.h>

// Problem-fixed sizes (reference: N=100000, F_IN=512, F_OUT=2).
#define NMAX 100000
#define FOUT 2
#define FIN 512

#define DEG_BLOCKS 160
#define GEMM_BLOCKS 1024
#define FUSED_BLOCKS (DEG_BLOCKS + GEMM_BLOCKS)  // 1184 = 148 SMs * 8 CTAs
#define EDGE_BLOCKS 1184

// __device__ globals are zero-initialized at module load; every kernel call
// restores them to zero before finishing (post re-zeros g_deg, head resets
// the scalar + ticket), so each graph replay sees identical initial state.
__device__ __align__(16) float g_deg[NMAX];
__device__ __align__(16) float g_dis[NMAX];
__device__ __align__(16) float g_h[NMAX * FOUT];    // raw x@W
__device__ __align__(16) float g_hs[NMAX * FOUT];   // h * dis (gather source)
__device__ __align__(16) float g_acc[NMAX * FOUT];  // self-loop + edge sums
__device__ float g_acc_scalar;
__device__ unsigned int g_ticket;

// ---------------------------------------------------------------------------
// K1 (fused, truly persistent): blocks [0, DEG_BLOCKS) grid-stride the deg
// segment-sum atomics (L2 pipe, start first); blocks [DEG_BLOCKS, 1184)
// grid-stride warp-per-row h = x @ W (DRAM streaming). launch_bounds forces
// 8 CTAs/SM so 1184 blocks are one wave: no wave transitions.
__global__ __launch_bounds__(256, 8) void fused_gemm_deg(
        const float* __restrict__ x, const float* __restrict__ W, int n,
        const int* __restrict__ col, const float* __restrict__ w, int E) {
    if ((int)blockIdx.x < DEG_BLOCKS) {
        // --- deg atomics: grid-stride over quads of edges ---
        int t0 = (int)blockIdx.x * 256 + threadIdx.x;
        const int nthr = DEG_BLOCKS * 256;
        int nq = E >> 2;
        for (int q = t0; q < nq; q += nthr) {
            int4 c4 = *(const int4*)(col + q * 4);
            float4 w4 = *(const float4*)(w + q * 4);
            atomicAdd(&g_deg[c4.x], w4.x);
            atomicAdd(&g_deg[c4.y], w4.y);
            atomicAdd(&g_deg[c4.z], w4.z);
            atomicAdd(&g_deg[c4.w], w4.w);
        }
        if (t0 == 0) {
            for (int e = nq * 4; e < E; ++e) atomicAdd(&g_deg[col[e]], w[e]);
        }
        return;
    }
    // --- GEMM: persistent warp-per-row ---
    __shared__ __align__(16) float sW[FIN * FOUT];
    for (int i = threadIdx.x; i < FIN * FOUT; i += blockDim.x) sW[i] = W[i];
    __syncthreads();

    int warp = threadIdx.x >> 5;
    int lane = threadIdx.x & 31;
    int wid0 = ((int)blockIdx.x - DEG_BLOCKS) * 8 + warp;
    const int wstride = GEMM_BLOCKS * 8;
    const float4* sW4 = (const float4*)sW;

#define ACCUM(v, q)                                                        \
    {                                                                      \
        float4 wa = sW4[2 * (q)];                                          \
        float4 wb = sW4[2 * (q) + 1];                                      \
        a0 += v.x * wa.x + v.y * wa.z + v.z * wb.x + v.w * wb.z;           \
        a1 += v.x * wa.y + v.y * wa.w + v.z * wb.y + v.w * wb.w;           \
    }
    for (int row = wid0; row < n; row += wstride) {
        const float4* xr = (const float4*)(x + (size_t)row * FIN);
        float a0 = 0.f, a1 = 0.f;
        // staged 2-deep to keep regs <= 32 for guaranteed 8 CTAs/SM
        float4 u0 = __ldg(xr + lane);
        float4 u1 = __ldg(xr + lane + 32);
        ACCUM(u0, lane)
        ACCUM(u1, lane + 32)
        u0 = __ldg(xr + lane + 64);
        u1 = __ldg(xr + lane + 96);
        ACCUM(u0, lane + 64)
        ACCUM(u1, lane + 96)

#pragma unroll
        for (int off = 16; off; off >>= 1) {
            a0 += __shfl_down_sync(0xffffffffu, a0, off);
            a1 += __shfl_down_sync(0xffffffffu, a1, off);
        }
        if (lane == 0) {
            g_h[2 * row + 0] = a0;
            g_h[2 * row + 1] = a1;
        }
    }
#undef ACCUM
}

// ---------------------------------------------------------------------------
// K2: dis = rsqrt(deg + 1); hs = h*dis; acc = hs (self-loop, weight 1);
// re-zero g_deg for the next replay.
__global__ void post_kernel(int n) {
    int i = blockIdx.x * blockDim.x + threadIdx.x;
    if (i >= n) return;
    float d = g_deg[i] + 1.0f;  // self-loop weight
    g_deg[i] = 0.0f;            // restore initial state for next call
    float dis = rsqrtf(d);      // d >= 1 always
    g_dis[i] = dis;
    float2 h = *(const float2*)(g_h + 2 * i);
    float2 hs = make_float2(h.x * dis, h.y * dis);
    *(float2*)(g_hs + 2 * i) = hs;
    *(float2*)(g_acc + 2 * i) = hs;
}

// ---------------------------------------------------------------------------
// K3: edge scatter (persistent): acc[col] += hs[row] * w. One random 8B
// gather + one v2 RED per edge; 4 edges/thread for gather ILP.
__global__ __launch_bounds__(256, 8) void edge_kernel(
        const int* __restrict__ row, const int* __restrict__ col,
        const float* __restrict__ w, int E) {
    int t0 = (int)blockIdx.x * 256 + threadIdx.x;
    const int nthr = EDGE_BLOCKS * 256;
    int nq = E >> 2;
    for (int q = t0; q < nq; q += nthr) {
        int base = q * 4;
        int4 r4 = *(const int4*)(row + base);
        int4 c4 = *(const int4*)(col + base);
        float4 w4 = *(const float4*)(w + base);
        float2 h0 = __ldg((const float2*)(g_hs + 2 * r4.x));
        float2 h1 = __ldg((const float2*)(g_hs + 2 * r4.y));
        float2 h2 = __ldg((const float2*)(g_hs + 2 * r4.z));
        float2 h3 = __ldg((const float2*)(g_hs + 2 * r4.w));
        asm volatile("red.global.add.v2.f32 [%0], {%1, %2};" ::
                     "l"(g_acc + 2 * c4.x), "f"(h0.x * w4.x), "f"(h0.y * w4.x) : "memory");
        asm volatile("red.global.add.v2.f32 [%0], {%1, %2};" ::
                     "l"(g_acc + 2 * c4.y), "f"(h1.x * w4.y), "f"(h1.y * w4.y) : "memory");
        asm volatile("red.global.add.v2.f32 [%0], {%1, %2};" ::
                     "l"(g_acc + 2 * c4.z), "f"(h2.x * w4.z), "f"(h2.y * w4.z) : "memory");
        asm volatile("red.global.add.v2.f32 [%0], {%1, %2};" ::
                     "l"(g_acc + 2 * c4.w), "f"(h3.x * w4.w), "f"(h3.y * w4.w) : "memory");
    }
    if (t0 == 0) {
        for (int e = nq * 4; e < E; ++e) {
            int r = row[e], c = col[e];
            float ww = w[e];
            float2 hv = __ldg((const float2*)(g_hs + 2 * r));
            asm volatile("red.global.add.v2.f32 [%0], {%1, %2};" ::
                         "l"(g_acc + 2 * c), "f"(hv.x * ww), "f"(hv.y * ww) : "memory");
        }
    }
}

// ---------------------------------------------------------------------------
// K4: head (+ fused final): relu(dis*acc + b) · fc_w -> g_acc_scalar; last
// block applies sigmoid into d_out and resets scalar state for next replay.
__global__ void head_kernel(const float* __restrict__ bvec,
                            const float* __restrict__ fcw,
                            const float* __restrict__ fcb,
                            float* __restrict__ out, int n, int nblocks) {
    int i = blockIdx.x * blockDim.x + threadIdx.x;
    float p = 0.f;
    if (i < n) {
        float dis = g_dis[i];
        float2 a = *(const float2*)(g_acc + 2 * i);
        float2 fw = *(const float2*)(fcw + 2 * i);
        float v0 = fmaxf(dis * a.x + bvec[0], 0.f);
        float v1 = fmaxf(dis * a.y + bvec[1], 0.f);
        p = v0 * fw.x + v1 * fw.y;
    }
#pragma unroll
    for (int off = 16; off; off >>= 1) p += __shfl_down_sync(0xffffffffu, p, off);
    __shared__ float ws[8];
    __shared__ bool is_last;
    int lane = threadIdx.x & 31, wid = threadIdx.x >> 5;
    if (lane == 0) ws[wid] = p;
    __syncthreads();
    if (wid == 0) {
        p = (lane < (blockDim.x >> 5)) ? ws[lane] : 0.f;
#pragma unroll
        for (int off = 4; off; off >>= 1) p += __shfl_down_sync(0xffffffffu, p, off);
        if (lane == 0) {
            atomicAdd(&g_acc_scalar, p);
            __threadfence();
            unsigned int t = atomicAdd(&g_ticket, 1u);
            is_last = (t == (unsigned int)(nblocks - 1));
        }
    }
    __syncthreads();
    if (is_last && threadIdx.x == 0) {
        float l = g_acc_scalar + fcb[0];
        out[0] = 1.f / (1.f + expf(-l));
        g_acc_scalar = 0.0f;   // restore initial state for next call
        g_ticket = 0u;
    }
}

// ---------------------------------------------------------------------------
extern "C" void kernel_launch(void* const* d_in, const int* in_sizes, int n_in,
                              void* d_out, int out_size) {
    const float* x   = (const float*)d_in[0];      // [N, F_IN]
    const int*   el  = (const int*)d_in[1];        // [2, E] int32 (JAX downcast)
    const float* ea  = (const float*)d_in[2];      // [E]
    const float* W   = (const float*)d_in[3];      // [F_IN, 2]
    const float* b   = (const float*)d_in[4];      // [2]
    const float* fcw = (const float*)d_in[5];      // [2N]
    const float* fcb = (const float*)d_in[6];      // scalar

    int E  = in_sizes[2];
    int n2 = in_sizes[5];
    int n  = n2 / FOUT;

    const int* rowp = el;
    const int* colp = el + E;

    int headB = (n + 255) / 256;

    fused_gemm_deg<<<FUSED_BLOCKS, 256>>>(x, W, n, colp, ea, E);
    post_kernel<<<(n + 255) / 256, 256>>>(n);
    edge_kernel<<<EDGE_BLOCKS, 256>>>(rowp, colp, ea, E);
    head_kernel<<<headB, 256>>>(b, fcw, fcb, (float*)d_out, n, headB);
}